// round 1
// baseline (speedup 1.0000x reference)
#include <cuda_runtime.h>

#define NBLK 128
#define NTHR 256
#define GSZ (NBLK * NTHR)
#define SMEM_FLOATS (12800 + NTHR)
#define SMEM_BYTES (SMEM_FLOATS * 4)

struct P {
  const float *x, *w1, *w2;
  const float *bn1g, *bn1b, *bn2g, *bn2b;
  const float *wc1, *bc1, *bn3g, *bn3b;
  const float *wc2, *bc2, *bn4g, *bn4b;
  const float *wc3, *bc3, *bn5g, *bn5b;
  const float *wf1, *bf1, *wf2, *bf2;
  float *out;
};

// ---- persistent-kernel scratch (device globals; no allocation) ----
__device__ unsigned int g_cnt = 0;
__device__ volatile unsigned int g_gen = 0;

__device__ float g_xs[131072];     // standardized inputs / pooled feats
__device__ float g_drive[131072];  // LCA input drive / pooled feats
__device__ float g_u[131072];      // LCA membrane potential
__device__ float g_recon[165888];  // factored-inhibition partial recons [NPART][4][C][36][36]
__device__ float g_h[131072];      // activations
__device__ float g_m[256];         // per-sample / per-channel mean
__device__ float g_rs[256];        // per-sample / per-channel inv-std
__device__ float g_fc[2048];       // fc1 output

// ---- software grid barrier (all 128 blocks co-resident on >=148 SMs) ----
// Reader-side __threadfence() emits CCTL.IVALL on sm_103a -> invalidates L1D,
// so normal loads after the barrier observe other blocks' writes.
__device__ __forceinline__ void grid_sync() {
  __syncthreads();
  if (threadIdx.x == 0) {
    unsigned int gen = g_gen;
    __threadfence();  // release: make my block's writes globally visible
    if (atomicAdd(&g_cnt, 1u) == (unsigned)(NBLK - 1)) {
      g_cnt = 0u;
      __threadfence();
      g_gen = gen + 1u;
    } else {
      while (g_gen == gen) { __nanosleep(64); }
      __threadfence();  // acquire: L1D invalidate before reading shared data
    }
  }
  __syncthreads();
}

__device__ __forceinline__ float block_reduce(float v, float *red) {
  red[threadIdx.x] = v;
  __syncthreads();
#pragma unroll
  for (int s = NTHR / 2; s > 0; s >>= 1) {
    if (threadIdx.x < s) red[threadIdx.x] += red[threadIdx.x + s];
    __syncthreads();
  }
  float r = red[0];
  __syncthreads();
  return r;
}

__device__ void zero_buf(float *b, int n) {
  for (int i = blockIdx.x * NTHR + threadIdx.x; i < n; i += GSZ) b[i] = 0.f;
}

// per-sample mean / 1/(std+1e-8) over `len` elements (B=4)
__device__ void sample_stats(const float *in, int len, float *red) {
  for (int n = blockIdx.x; n < 4; n += NBLK) {
    const float *p = in + n * len;
    float s = 0.f, ss = 0.f;
    for (int i = threadIdx.x; i < len; i += NTHR) {
      float v = p[i];
      s += v;
      ss += v * v;
    }
    s = block_reduce(s, red);
    ss = block_reduce(ss, red);
    if (threadIdx.x == 0) {
      float m = s / (float)len;
      float var = fmaxf(ss / (float)len - m * m, 0.f);
      g_m[n] = m;
      g_rs[n] = 1.f / (sqrtf(var) + 1e-8f);
    }
    __syncthreads();
  }
}

__device__ void standardize(const float *in, float *out, int len) {
  for (int i = blockIdx.x * NTHR + threadIdx.x; i < 4 * len; i += GSZ) {
    int n = i / len;
    out[i] = (in[i] - g_m[n]) * g_rs[n];
  }
}

// generic 5x5 "same" conv (cross-correlation), optional bias+relu. NCHW, B=4.
__device__ void conv5x5(const float *__restrict__ in, const float *__restrict__ w,
                        const float *__restrict__ bias, float *__restrict__ out,
                        int Cin, int Cout, int HW, bool do_relu) {
  int npix = HW * HW;
  int N = 4 * Cout * npix;
  for (int idx = blockIdx.x * NTHR + threadIdx.x; idx < N; idx += GSZ) {
    int x = idx % HW;
    int t = idx / HW;
    int y = t % HW;
    t /= HW;
    int f = t % Cout;
    int n = t / Cout;
    float acc = bias ? bias[f] : 0.f;
    const float *wb = w + f * Cin * 25;
    for (int c = 0; c < Cin; ++c) {
      const float *ib = in + (n * Cin + c) * npix;
      const float *wc = wb + c * 25;
#pragma unroll
      for (int ky = 0; ky < 5; ++ky) {
        int yy = y + ky - 2;
        if ((unsigned)yy >= (unsigned)HW) continue;
#pragma unroll
        for (int kx = 0; kx < 5; ++kx) {
          int xx = x + kx - 2;
          if ((unsigned)xx >= (unsigned)HW) continue;
          acc += ib[yy * HW + xx] * wc[ky * 5 + kx];
        }
      }
    }
    out[idx] = do_relu ? fmaxf(acc, 0.f) : acc;
  }
}

__device__ void maxpool2(const float *__restrict__ in, float *__restrict__ out,
                         int C, int H) {
  int Ho = H / 2;
  int N = 4 * C * Ho * Ho;
  for (int idx = blockIdx.x * NTHR + threadIdx.x; idx < N; idx += GSZ) {
    int xo = idx % Ho;
    int t = idx / Ho;
    int yo = t % Ho;
    t /= Ho;  // t = n*C + c
    const float *ib = in + t * H * H + (yo * 2) * H + xo * 2;
    out[idx] = fmaxf(fmaxf(ib[0], ib[1]), fmaxf(ib[H], ib[H + 1]));
  }
}

// BatchNorm batch statistics over (N,H,W) per channel (training-mode math)
__device__ void bn_stats(const float *in, int C, int npix, float *red) {
  int cnt = 4 * npix;
  for (int c = blockIdx.x; c < C; c += NBLK) {
    float s = 0.f, ss = 0.f;
    for (int i = threadIdx.x; i < cnt; i += NTHR) {
      int n = i / npix, pp = i % npix;
      float v = in[(n * C + c) * npix + pp];
      s += v;
      ss += v * v;
    }
    s = block_reduce(s, red);
    ss = block_reduce(ss, red);
    if (threadIdx.x == 0) {
      float m = s / (float)cnt;
      float var = fmaxf(ss / (float)cnt - m * m, 0.f);
      g_m[c] = m;
      g_rs[c] = rsqrtf(var + 1e-5f);
    }
    __syncthreads();
  }
}

__device__ void bn_apply(float *buf, int C, int npix, const float *gam, const float *bet) {
  int N = 4 * C * npix;
  for (int i = blockIdx.x * NTHR + threadIdx.x; i < N; i += GSZ) {
    int c = (i / npix) % C;
    buf[i] = (buf[i] - g_m[c]) * g_rs[c] * gam[c] + bet[c];
  }
}

__device__ void relu_shift(const float *u, float *out, int n) {
  for (int i = blockIdx.x * NTHR + threadIdx.x; i < n; i += GSZ)
    out[i] = fmaxf(u[i] - 0.5f, 0.f);
}

// ===================== factored LCA iteration =====================
// inhib = conv(a, G), G = W * W (Gram), factored exactly as:
//   recon_ext[n,c,Y,X] = sum_{f,ky,kx} w[f,c,ky,kx] * a[n,f,Y-ky,X-kx]   (Y,X in [0,36))
//   inhib[n,f,y,x]     = sum_{c,ky,kx} w[f,c,ky,kx] * recon_ext[n,c,y+ky,x+kx]
// a = relu(u - 0.5) computed on the fly. F split into NPART partial recons
// for thread-level parallelism; phase B sums the partials.

template <int F, int C, int NPART>
__device__ void lca_phaseA(const float *__restrict__ u, float *__restrict__ recon,
                           const float *__restrict__ sw) {
  constexpr int FP = F / NPART;
  const int NJOB = NPART * 4 * 1296;
  for (int idx = blockIdx.x * NTHR + threadIdx.x; idx < NJOB; idx += GSZ) {
    int pix = idx % 1296;
    int t = idx / 1296;  // part*4 + n
    int n = t & 3;
    int part = t >> 2;
    int Y = pix / 36, X = pix % 36;
    float acc[C];
#pragma unroll
    for (int c = 0; c < C; ++c) acc[c] = 0.f;
    for (int ff = 0; ff < FP; ++ff) {
      int f = part * FP + ff;
      const float *ub = u + (n * F + f) * 1024;
      const float *wf = sw + f * C * 25;
#pragma unroll
      for (int ky = 0; ky < 5; ++ky) {
        int y = Y - ky;
        if ((unsigned)y >= 32u) continue;
#pragma unroll
        for (int kx = 0; kx < 5; ++kx) {
          int x = X - kx;
          if ((unsigned)x >= 32u) continue;
          float a = fmaxf(ub[y * 32 + x] - 0.5f, 0.f);
#pragma unroll
          for (int c = 0; c < C; ++c) acc[c] += a * wf[c * 25 + ky * 5 + kx];
        }
      }
    }
    float *rb = recon + t * C * 1296 + pix;
#pragma unroll
    for (int c = 0; c < C; ++c) rb[c * 1296] = acc[c];
  }
}

template <int F, int C, int FG>  // NPART fixed at 2
__device__ void lca_phaseB(float *__restrict__ u, const float *__restrict__ recon,
                           const float *__restrict__ drive, const float *__restrict__ sw) {
  constexpr int NG = F / FG;
  const int NJOB = 4 * NG * 1024;
  for (int idx = blockIdx.x * NTHR + threadIdx.x; idx < NJOB; idx += GSZ) {
    int pix = idx % 1024;
    int t = idx / 1024;  // n*NG + g
    int g = t % NG;
    int n = t / NG;
    int y = pix >> 5, x = pix & 31;
    float acc[FG];
#pragma unroll
    for (int j = 0; j < FG; ++j) acc[j] = 0.f;
    for (int c = 0; c < C; ++c) {
      const float *rb0 = recon + (n * C + c) * 1296;
      const float *rb1 = recon + ((4 + n) * C + c) * 1296;
      const float *wc = sw + (g * FG * C + c) * 25;
#pragma unroll
      for (int ky = 0; ky < 5; ++ky) {
        int off = (y + ky) * 36 + x;
#pragma unroll
        for (int kx = 0; kx < 5; ++kx) {
          float rv = rb0[off + kx] + rb1[off + kx];
          const float *wp = wc + ky * 5 + kx;
#pragma unroll
          for (int j = 0; j < FG; ++j) acc[j] += rv * wp[j * C * 25];
        }
      }
    }
#pragma unroll
    for (int j = 0; j < FG; ++j) {
      int f = g * FG + j;
      int i = (n * F + f) * 1024 + pix;
      float uv = u[i];
      float a = fmaxf(uv - 0.5f, 0.f);
      u[i] = uv + 0.001f * (drive[i] - uv - acc[j] + a);
    }
  }
}

__device__ void fc(const float *__restrict__ in, const float *__restrict__ w,
                   const float *__restrict__ bias, float *__restrict__ out,
                   int K, int J, bool do_relu) {
  int N = 4 * J;
  for (int idx = blockIdx.x * NTHR + threadIdx.x; idx < N; idx += GSZ) {
    int j = idx % J, n = idx / J;
    float acc = bias[j];
    const float *wr = w + j * K;
    const float *ir = in + n * K;
    for (int k = 0; k < K; ++k) acc += ir[k] * wr[k];
    out[idx] = do_relu ? fmaxf(acc, 0.f) : acc;
  }
}

// ===================== the whole network, one persistent kernel =====================
__global__ void __launch_bounds__(NTHR, 1) splitnn_kernel(P p) {
  extern __shared__ float smem[];
  float *sw = smem;            // 12800 floats: LCA dictionary
  float *red = smem + 12800;   // 256 floats: reduction scratch

  // ---- standardize input, drive1, u=0 ----
  sample_stats(p.x, 3072, red);
  grid_sync();
  standardize(p.x, g_xs, 3072);
  zero_buf(g_u, 65536);
  grid_sync();
  conv5x5(g_xs, p.w1, nullptr, g_drive, 3, 16, 32, false);
  for (int i = threadIdx.x; i < 16 * 3 * 25; i += NTHR) sw[i] = p.w1[i];
  grid_sync();

  // ---- LCA1: F=16, C=3, 500 iters ----
  for (int it = 0; it < 500; ++it) {
    lca_phaseA<16, 3, 2>(g_u, g_recon, sw);
    grid_sync();
    lca_phaseB<16, 3, 8>(g_u, g_recon, g_drive, sw);
    grid_sync();
  }
  relu_shift(g_u, g_h, 65536);
  grid_sync();
  bn_stats(g_h, 16, 1024, red);
  grid_sync();
  bn_apply(g_h, 16, 1024, p.bn1g, p.bn1b);
  grid_sync();

  // ---- standardize, drive2, u=0 ----
  sample_stats(g_h, 16384, red);
  grid_sync();
  standardize(g_h, g_xs, 16384);
  zero_buf(g_u, 131072);
  grid_sync();
  conv5x5(g_xs, p.w2, nullptr, g_drive, 16, 32, 32, false);
  for (int i = threadIdx.x; i < 32 * 16 * 25; i += NTHR) sw[i] = p.w2[i];
  grid_sync();

  // ---- LCA2: F=32, C=16, 500 iters ----
  for (int it = 0; it < 500; ++it) {
    lca_phaseA<32, 16, 2>(g_u, g_recon, sw);
    grid_sync();
    lca_phaseB<32, 16, 8>(g_u, g_recon, g_drive, sw);
    grid_sync();
  }
  relu_shift(g_u, g_h, 131072);
  grid_sync();
  maxpool2(g_h, g_xs, 32, 32);  // -> [4,32,16,16]
  grid_sync();
  bn_stats(g_xs, 32, 256, red);
  grid_sync();
  bn_apply(g_xs, 32, 256, p.bn2g, p.bn2b);
  grid_sync();

  // ---- conv tail ----
  conv5x5(g_xs, p.wc1, p.bc1, g_h, 32, 64, 16, true);
  grid_sync();
  maxpool2(g_h, g_drive, 64, 16);  // -> [4,64,8,8]
  grid_sync();
  bn_stats(g_drive, 64, 64, red);
  grid_sync();
  bn_apply(g_drive, 64, 64, p.bn3g, p.bn3b);
  grid_sync();
  conv5x5(g_drive, p.wc2, p.bc2, g_h, 64, 128, 8, true);
  grid_sync();
  maxpool2(g_h, g_xs, 128, 8);  // -> [4,128,4,4]
  grid_sync();
  bn_stats(g_xs, 128, 16, red);
  grid_sync();
  bn_apply(g_xs, 128, 16, p.bn4g, p.bn4b);
  grid_sync();
  conv5x5(g_xs, p.wc3, p.bc3, g_h, 128, 256, 4, true);
  grid_sync();
  maxpool2(g_h, g_drive, 256, 4);  // -> [4,256,2,2] == flat [4,1024]
  grid_sync();
  bn_stats(g_drive, 256, 4, red);
  grid_sync();
  bn_apply(g_drive, 256, 4, p.bn5g, p.bn5b);
  grid_sync();

  // ---- classifier ----
  fc(g_drive, p.wf1, p.bf1, g_fc, 1024, 512, true);
  grid_sync();
  fc(g_fc, p.wf2, p.bf2, p.out, 512, 10, false);
}

extern "C" void kernel_launch(void *const *d_in, const int *in_sizes, int n_in,
                              void *d_out, int out_size) {
  (void)in_sizes;
  (void)n_in;
  (void)out_size;
  P p;
  p.x = (const float *)d_in[0];
  p.w1 = (const float *)d_in[1];
  p.w2 = (const float *)d_in[2];
  p.bn1g = (const float *)d_in[3];
  p.bn1b = (const float *)d_in[4];
  p.bn2g = (const float *)d_in[5];
  p.bn2b = (const float *)d_in[6];
  p.wc1 = (const float *)d_in[7];
  p.bc1 = (const float *)d_in[8];
  p.bn3g = (const float *)d_in[9];
  p.bn3b = (const float *)d_in[10];
  p.wc2 = (const float *)d_in[11];
  p.bc2 = (const float *)d_in[12];
  p.bn4g = (const float *)d_in[13];
  p.bn4b = (const float *)d_in[14];
  p.wc3 = (const float *)d_in[15];
  p.bc3 = (const float *)d_in[16];
  p.bn5g = (const float *)d_in[17];
  p.bn5b = (const float *)d_in[18];
  p.wf1 = (const float *)d_in[19];
  p.bf1 = (const float *)d_in[20];
  p.wf2 = (const float *)d_in[21];
  p.bf2 = (const float *)d_in[22];
  p.out = (float *)d_out;

  cudaFuncSetAttribute(reinterpret_cast<const void *>(splitnn_kernel),
                       cudaFuncAttributeMaxDynamicSharedMemorySize, SMEM_BYTES);
  splitnn_kernel<<<NBLK, NTHR, SMEM_BYTES>>>(p);
}